// round 6
// baseline (speedup 1.0000x reference)
#include <cuda_runtime.h>
#include <cuda_bf16.h>
#include <cstdint>

typedef unsigned long long ull;

#define N_PTS 8192
#define DIM   128
#define EMB   16

// Scratch (device globals — no allocation allowed)
__device__ __align__(16) float g_z[N_PTS * EMB];
__device__ float g_sq[N_PTS];
__device__ float g_rowsum[N_PTS];

__device__ __forceinline__ float frcp(float x) {
    float r;
    asm("rcp.approx.ftz.f32 %0, %1;" : "=f"(r) : "f"(x));
    return r;
}
__device__ __forceinline__ void fma2(ull &d, ull a, ull b) {
    asm("fma.rn.f32x2 %0, %1, %2, %0;" : "+l"(d) : "l"(a), "l"(b));
}
__device__ __forceinline__ void unpack2(ull v, float &lo, float &hi) {
    asm("mov.b64 {%0, %1}, %2;" : "=f"(lo), "=f"(hi) : "l"(v));
}
__device__ __forceinline__ ull bcast2(float x) {
    ull v;
    asm("mov.b64 %0, {%1, %1};" : "=l"(v) : "f"(x));
    return v;
}

// triangular linear block id -> (row r, col c) with c >= r, 128x128 tile grid
__device__ __forceinline__ int tri_off128(int r) { return (r * (257 - r)) >> 1; }
__device__ __forceinline__ void tri_decode128(int b, int &r, int &c) {
    int rr = (int)((257.0f - sqrtf(66049.0f - 8.0f * (float)b)) * 0.5f);
    if (rr < 0) rr = 0;
    if (rr > 127) rr = 127;
    while (rr < 127 && tri_off128(rr + 1) <= b) rr++;
    while (rr > 0 && tri_off128(rr) > b) rr--;
    r = rr;
    c = rr + (b - tri_off128(rr));
}

// ===========================================================================
// Encoder: 256 blocks x 256 threads, 32 rows/block.
// ===========================================================================
#define OFF_W1   0            // float[128][64]   32768
#define OFF_X    32768        // float[32][132]   16896
#define OFF_W2   49664        // float[64][32]     8192
#define OFF_W3   57856        // float[32][16]     2048
#define OFF_W4   59904        // float[16][16]     1024
#define OFF_B1   60928        // 256
#define OFF_B2   61184        // 128
#define OFF_B3   61312        // 64
#define OFF_B4   61376        // 64
#define OFF_E1   61440        // float[32][68]     8704
#define OFF_E2   70144        // float[32][36]     4608
#define OFF_E3   74752        // float[32][20]     2560
#define ENC_SMEM 77312

__global__ __launch_bounds__(256) void encoder_kernel(
    const float* __restrict__ x,
    const float* __restrict__ W1, const float* __restrict__ b1,
    const float* __restrict__ W2, const float* __restrict__ b2,
    const float* __restrict__ W3, const float* __restrict__ b3,
    const float* __restrict__ W4, const float* __restrict__ b4)
{
    extern __shared__ char dyn[];
    float* sW1 = (float*)(dyn + OFF_W1);
    float* sx  = (float*)(dyn + OFF_X);
    float* sW2 = (float*)(dyn + OFF_W2);
    float* sW3 = (float*)(dyn + OFF_W3);
    float* sW4 = (float*)(dyn + OFF_W4);
    float* sb1 = (float*)(dyn + OFF_B1);
    float* sb2 = (float*)(dyn + OFF_B2);
    float* sb3 = (float*)(dyn + OFF_B3);
    float* sb4 = (float*)(dyn + OFF_B4);
    float* e1  = (float*)(dyn + OFF_E1);
    float* e2  = (float*)(dyn + OFF_E2);
    float* e3  = (float*)(dyn + OFF_E3);

    const int t  = threadIdx.x;
    const int i0 = blockIdx.x * 32;

    int gid = blockIdx.x * 256 + t;
    if (gid < N_PTS) g_rowsum[gid] = 0.0f;

    {
        const ulonglong2* s = (const ulonglong2*)W1;
        ulonglong2* d = (ulonglong2*)sW1;
        #pragma unroll
        for (int r = 0; r < 8; r++) d[t + r * 256] = s[t + r * 256];
    }
    {
        const float4* x4 = (const float4*)(x + (size_t)i0 * DIM);
        #pragma unroll
        for (int r = 0; r < 4; r++) {
            int idx = t + r * 256;
            int row = idx >> 5, c = idx & 31;
            *(float4*)&sx[row * 132 + c * 4] = x4[idx];
        }
    }
    {
        const float4* s = (const float4*)W2;
        float4* d = (float4*)sW2;
        d[t] = s[t]; d[t + 256] = s[t + 256];
    }
    if (t < 128) ((float4*)sW3)[t] = ((const float4*)W3)[t];
    if (t < 64)  ((float4*)sW4)[t] = ((const float4*)W4)[t];
    if (t < 64) sb1[t] = b1[t];
    if (t < 32) sb2[t] = b2[t];
    if (t < 16) { sb3[t] = b3[t]; sb4[t] = b4[t]; }
    __syncthreads();

    {
        const int og = t & 15, rg = t >> 4;
        const int r0 = rg * 2, r1 = r0 + 1;
        ull a00 = ((const ull*)sb1)[og * 2];
        ull a01 = ((const ull*)sb1)[og * 2 + 1];
        ull a10 = a00, a11 = a01;
        // second pair of chains for ILP (even/odd k4)
        ull c00 = 0ull, c01 = 0ull, c10 = 0ull, c11 = 0ull;
        const ull* w1u = (const ull*)sW1;
        #pragma unroll 4
        for (int k4 = 0; k4 < 32; k4 += 2) {
            float4 x0 = *(const float4*)&sx[r0 * 132 + k4 * 4];
            float4 x1 = *(const float4*)&sx[r1 * 132 + k4 * 4];
            float4 y0 = *(const float4*)&sx[r0 * 132 + k4 * 4 + 4];
            float4 y1 = *(const float4*)&sx[r1 * 132 + k4 * 4 + 4];
            float xs0[4] = {x0.x, x0.y, x0.z, x0.w};
            float xs1[4] = {x1.x, x1.y, x1.z, x1.w};
            float ys0[4] = {y0.x, y0.y, y0.z, y0.w};
            float ys1[4] = {y1.x, y1.y, y1.z, y1.w};
            #pragma unroll
            for (int c = 0; c < 4; c++) {
                ulonglong2 w = *(const ulonglong2*)&w1u[(k4 * 4 + c) * 32 + og * 2];
                ull v0 = bcast2(xs0[c]);
                ull v1 = bcast2(xs1[c]);
                fma2(a00, v0, w.x); fma2(a01, v0, w.y);
                fma2(a10, v1, w.x); fma2(a11, v1, w.y);
                ulonglong2 u = *(const ulonglong2*)&w1u[(k4 * 4 + 4 + c) * 32 + og * 2];
                ull u0 = bcast2(ys0[c]);
                ull u1 = bcast2(ys1[c]);
                fma2(c00, u0, u.x); fma2(c01, u0, u.y);
                fma2(c10, u1, u.x); fma2(c11, u1, u.y);
            }
        }
        float p, q, r, s, p2, q2, r2, s2;
        unpack2(a00, p, q); unpack2(a01, r, s);
        { float e, f, g, h; unpack2(c00, e, f); unpack2(c01, g, h); p += e; q += f; r += g; s += h; }
        *(float4*)&e1[r0 * 68 + og * 4] =
            make_float4(fmaxf(p, 0.f), fmaxf(q, 0.f), fmaxf(r, 0.f), fmaxf(s, 0.f));
        unpack2(a10, p2, q2); unpack2(a11, r2, s2);
        { float e, f, g, h; unpack2(c10, e, f); unpack2(c11, g, h); p2 += e; q2 += f; r2 += g; s2 += h; }
        *(float4*)&e1[r1 * 68 + og * 4] =
            make_float4(fmaxf(p2, 0.f), fmaxf(q2, 0.f), fmaxf(r2, 0.f), fmaxf(s2, 0.f));
    }
    __syncthreads();

    const int row = t >> 3;
    const int e   = t & 7;

    {
        ull c0 = ((const ull*)sb2)[e * 2];
        ull c1 = ((const ull*)sb2)[e * 2 + 1];
        const float* h1r = &e1[row * 68];
        const ull* w2u = (const ull*)sW2;
        #pragma unroll 4
        for (int k4 = 0; k4 < 16; k4++) {
            float4 h = *(const float4*)&h1r[k4 * 4];
            float hs[4] = {h.x, h.y, h.z, h.w};
            #pragma unroll
            for (int c = 0; c < 4; c++) {
                ulonglong2 w = *(const ulonglong2*)&w2u[(k4 * 4 + c) * 16 + e * 2];
                ull hb = bcast2(hs[c]);
                fma2(c0, hb, w.x); fma2(c1, hb, w.y);
            }
        }
        float p, q, r, s;
        unpack2(c0, p, q); unpack2(c1, r, s);
        *(float4*)&e2[row * 36 + e * 4] =
            make_float4(fmaxf(p, 0.f), fmaxf(q, 0.f), fmaxf(r, 0.f), fmaxf(s, 0.f));
    }
    __syncthreads();

    {
        ull d0 = ((const ull*)sb3)[e];
        const float* h2r = &e2[row * 36];
        const ull* w3u = (const ull*)sW3;
        #pragma unroll
        for (int k4 = 0; k4 < 8; k4++) {
            float4 h = *(const float4*)&h2r[k4 * 4];
            float hs[4] = {h.x, h.y, h.z, h.w};
            #pragma unroll
            for (int c = 0; c < 4; c++) {
                ull w = w3u[(k4 * 4 + c) * 8 + e];
                fma2(d0, bcast2(hs[c]), w);
            }
        }
        float p, q;
        unpack2(d0, p, q);
        *(float2*)&e3[row * 20 + e * 2] = make_float2(fmaxf(p, 0.f), fmaxf(q, 0.f));
    }
    __syncthreads();

    {
        ull f0 = ((const ull*)sb4)[e];
        const float* h3r = &e3[row * 20];
        const ull* w4u = (const ull*)sW4;
        #pragma unroll
        for (int k4 = 0; k4 < 4; k4++) {
            float4 h = *(const float4*)&h3r[k4 * 4];
            float hs[4] = {h.x, h.y, h.z, h.w};
            #pragma unroll
            for (int c = 0; c < 4; c++) {
                ull w = w4u[(k4 * 4 + c) * 8 + e];
                fma2(f0, bcast2(hs[c]), w);
            }
        }
        float z0, z1;
        unpack2(f0, z0, z1);
        *(float2*)&g_z[(size_t)(i0 + row) * EMB + e * 2] = make_float2(z0, z1);

        float ps = z0 * z0 + z1 * z1;
        ps += __shfl_xor_sync(0xffffffffu, ps, 1);
        ps += __shfl_xor_sync(0xffffffffu, ps, 2);
        ps += __shfl_xor_sync(0xffffffffu, ps, 4);
        if (e == 0) g_sq[i0 + row] = ps;
    }
}

// ===========================================================================
// Shared staging for 64-row tiles: zsm[8][66] (k2-major ull pairs)
// ===========================================================================
__device__ __forceinline__ void stage64(ull (*zsm)[66], int r0, int t) {
    const float4* gz4 = (const float4*)g_z;
    int row = t >> 2, q = t & 3;
    float4 f = gz4[(size_t)(r0 + row) * 4 + q];
    *(float2*)&zsm[2 * q][row]     = make_float2(f.x, f.y);
    *(float2*)&zsm[2 * q + 1][row] = make_float2(f.z, f.w);
}

// inner 4i x 4j mma: acc[16], b at tx+16c, a at ty*4..
__device__ __forceinline__ void mma44(ull* acc, const ull (*zasm)[66],
                                      const ull (*zbsm)[66], int tx, int ty) {
    #pragma unroll
    for (int k2 = 0; k2 < 8; k2++) {
        ull b0 = zbsm[k2][tx];
        ull b1 = zbsm[k2][tx + 16];
        ull b2 = zbsm[k2][tx + 32];
        ull b3 = zbsm[k2][tx + 48];
        ulonglong2 a01 = *(const ulonglong2*)&zasm[k2][ty * 4];
        ulonglong2 a23 = *(const ulonglong2*)&zasm[k2][ty * 4 + 2];
        ull av[4] = {a01.x, a01.y, a23.x, a23.y};
        #pragma unroll
        for (int ii = 0; ii < 4; ii++) {
            fma2(acc[ii * 4 + 0], av[ii], b0);
            fma2(acc[ii * 4 + 1], av[ii], b1);
            fma2(acc[ii * 4 + 2], av[ii], b2);
            fma2(acc[ii * 4 + 3], av[ii], b3);
        }
    }
}

// ===========================================================================
// Kernel 2: symmetric row sums. triangular grid over 64x64 tiles (8256 blk).
// ===========================================================================
__global__ __launch_bounds__(256) void rowsum_kernel()
{
    int by, bx;
    tri_decode128(blockIdx.x, by, bx);

    __shared__ ull zasm[8][66];
    __shared__ ull zbsm[8][66];
    __shared__ float sqis[64];
    __shared__ float sqjs[64];
    __shared__ float rowacc[64];
    __shared__ float colacc[64];

    const int t = threadIdx.x, tx = t & 15, ty = t >> 4;
    const int i0 = by * 64, j0 = bx * 64;
    const bool diag = (bx == by);

    stage64(zasm, i0, t);
    stage64(zbsm, j0, t);
    if (t < 64) sqis[t] = g_sq[i0 + t];
    else if (t < 128) sqjs[t - 64] = g_sq[j0 + (t - 64)];
    else if (t < 192) colacc[t - 128] = 0.0f;
    __syncthreads();

    ull acc[16];
    #pragma unroll
    for (int m = 0; m < 16; m++) acc[m] = 0ull;
    mma44(acc, zasm, zbsm, tx, ty);

    const float sj0 = sqjs[tx];
    const float sj1 = sqjs[tx + 16];
    const float sj2 = sqjs[tx + 32];
    const float sj3 = sqjs[tx + 48];
    float colp0 = 0.f, colp1 = 0.f, colp2 = 0.f, colp3 = 0.f;

    #pragma unroll
    for (int ii = 0; ii < 4; ii++) {
        const float si = sqis[ty * 4 + ii];
        float lo, hi, dot, dist, n0, n1, n2, n3;
        unpack2(acc[ii * 4 + 0], lo, hi); dot = lo + hi;
        dist = fmaxf(fmaf(-2.0f, dot, si + sj0), 0.0f); n0 = frcp(1.0f + dist);
        unpack2(acc[ii * 4 + 1], lo, hi); dot = lo + hi;
        dist = fmaxf(fmaf(-2.0f, dot, si + sj1), 0.0f); n1 = frcp(1.0f + dist);
        unpack2(acc[ii * 4 + 2], lo, hi); dot = lo + hi;
        dist = fmaxf(fmaf(-2.0f, dot, si + sj2), 0.0f); n2 = frcp(1.0f + dist);
        unpack2(acc[ii * 4 + 3], lo, hi); dot = lo + hi;
        dist = fmaxf(fmaf(-2.0f, dot, si + sj3), 0.0f); n3 = frcp(1.0f + dist);

        float v = (n0 + n1) + (n2 + n3);
        v += __shfl_xor_sync(0xffffffffu, v, 1);
        v += __shfl_xor_sync(0xffffffffu, v, 2);
        v += __shfl_xor_sync(0xffffffffu, v, 4);
        v += __shfl_xor_sync(0xffffffffu, v, 8);
        if (tx == 0) rowacc[ty * 4 + ii] = v;

        colp0 += n0; colp1 += n1; colp2 += n2; colp3 += n3;
    }

    if (!diag) {
        colp0 += __shfl_xor_sync(0xffffffffu, colp0, 16);
        colp1 += __shfl_xor_sync(0xffffffffu, colp1, 16);
        colp2 += __shfl_xor_sync(0xffffffffu, colp2, 16);
        colp3 += __shfl_xor_sync(0xffffffffu, colp3, 16);
        if ((t & 16) == 0) {
            atomicAdd(&colacc[tx],      colp0);
            atomicAdd(&colacc[tx + 16], colp1);
            atomicAdd(&colacc[tx + 32], colp2);
            atomicAdd(&colacc[tx + 48], colp3);
        }
    }
    __syncthreads();

    if (t < 64) atomicAdd(&g_rowsum[i0 + t], rowacc[t]);
    if (!diag && t >= 64 && t < 128) atomicAdd(&g_rowsum[j0 + (t - 64)], colacc[t - 64]);
}

// ===========================================================================
// Kernel 3: symmetric writer. triangular grid (8256 blocks), 256 threads.
// Numerators staged in snum; store phase uses STG.128 exclusively.
// ===========================================================================
__global__ __launch_bounds__(256) void writer_kernel(float* __restrict__ out)
{
    int by, bx;
    tri_decode128(blockIdx.x, by, bx);

    __shared__ ull zasm[8][66];
    __shared__ ull zbsm[8][66];
    __shared__ float snum[64 * 68];
    __shared__ float sqis[64];
    __shared__ float sqjs[64];
    __shared__ float rinvi[64];
    __shared__ float rinvj[64];

    const int t = threadIdx.x, tx = t & 15, ty = t >> 4;
    const int i0 = by * 64, j0 = bx * 64;
    const bool diag = (bx == by);

    stage64(zasm, i0, t);
    stage64(zbsm, j0, t);
    if (t < 64) sqis[t] = g_sq[i0 + t];
    else if (t < 128) sqjs[t - 64] = g_sq[j0 + (t - 64)];
    else if (t < 192) rinvi[t - 128] = frcp(g_rowsum[i0 + (t - 128)]);
    else rinvj[t - 192] = frcp(g_rowsum[j0 + (t - 192)]);
    __syncthreads();

    ull acc[16];
    #pragma unroll
    for (int m = 0; m < 16; m++) acc[m] = 0ull;
    mma44(acc, zasm, zbsm, tx, ty);

    const float sj0 = sqjs[tx];
    const float sj1 = sqjs[tx + 16];
    const float sj2 = sqjs[tx + 32];
    const float sj3 = sqjs[tx + 48];

    #pragma unroll
    for (int ii = 0; ii < 4; ii++) {
        const int irow = ty * 4 + ii;
        const float si = sqis[irow];
        float* srow = &snum[irow * 68];
        float lo, hi, dot, dist;

        unpack2(acc[ii * 4 + 0], lo, hi); dot = lo + hi;
        dist = fmaxf(fmaf(-2.0f, dot, si + sj0), 0.0f); srow[tx] = frcp(1.0f + dist);
        unpack2(acc[ii * 4 + 1], lo, hi); dot = lo + hi;
        dist = fmaxf(fmaf(-2.0f, dot, si + sj1), 0.0f); srow[tx + 16] = frcp(1.0f + dist);
        unpack2(acc[ii * 4 + 2], lo, hi); dot = lo + hi;
        dist = fmaxf(fmaf(-2.0f, dot, si + sj2), 0.0f); srow[tx + 32] = frcp(1.0f + dist);
        unpack2(acc[ii * 4 + 3], lo, hi); dot = lo + hi;
        dist = fmaxf(fmaf(-2.0f, dot, si + sj3), 0.0f); srow[tx + 48] = frcp(1.0f + dist);
    }
    __syncthreads();

    // store phase: all STG.128
    {
        const int r  = t >> 2;        // row within tile
        const int qq = t & 3;         // 16-col group
        const float rvi = rinvi[r];
        float* orow = &out[(size_t)(i0 + r) * N_PTS + j0 + qq * 16];
        const float* srow = &snum[r * 68 + qq * 16];
        #pragma unroll
        for (int m = 0; m < 4; m++) {
            float4 v = *(const float4*)&srow[m * 4];
            v.x *= rvi; v.y *= rvi; v.z *= rvi; v.w *= rvi;
            *(float4*)&orow[m * 4] = v;
        }

        if (!diag) {
            const float rvj = rinvj[r];
            float* otrow = &out[(size_t)(j0 + r) * N_PTS + i0 + qq * 16];
            #pragma unroll
            for (int m = 0; m < 4; m++) {
                const int ib = qq * 16 + m * 4;
                float4 v;
                v.x = snum[(ib + 0) * 68 + r] * rvj;
                v.y = snum[(ib + 1) * 68 + r] * rvj;
                v.z = snum[(ib + 2) * 68 + r] * rvj;
                v.w = snum[(ib + 3) * 68 + r] * rvj;
                *(float4*)&otrow[m * 4] = v;
            }
        }
    }
}

// ---------------------------------------------------------------------------
extern "C" void kernel_launch(void* const* d_in, const int* in_sizes, int n_in,
                              void* d_out, int out_size)
{
    const float* x  = (const float*)d_in[0];
    const float* W1 = (const float*)d_in[1];
    const float* b1 = (const float*)d_in[2];
    const float* W2 = (const float*)d_in[3];
    const float* b2 = (const float*)d_in[4];
    const float* W3 = (const float*)d_in[5];
    const float* b3 = (const float*)d_in[6];
    const float* W4 = (const float*)d_in[7];
    const float* b4 = (const float*)d_in[8];
    float* out = (float*)d_out;

    cudaFuncSetAttribute(encoder_kernel,
                         cudaFuncAttributeMaxDynamicSharedMemorySize, ENC_SMEM);
    cudaFuncSetAttribute(encoder_kernel,
                         cudaFuncAttributePreferredSharedMemoryCarveout, 100);

    const int n_tri = (128 * 129) / 2;  // 8256

    encoder_kernel<<<N_PTS / 32, 256, ENC_SMEM>>>(x, W1, b1, W2, b2, W3, b3, W4, b4);
    rowsum_kernel<<<n_tri, 256>>>();
    writer_kernel<<<n_tri, 256>>>(out);
}

// round 7
// speedup vs baseline: 1.3020x; 1.3020x over previous
#include <cuda_runtime.h>
#include <cuda_bf16.h>
#include <cstdint>

typedef unsigned long long ull;

#define N_PTS 8192
#define DIM   128
#define EMB   16

// Scratch (device globals — no allocation allowed)
__device__ __align__(16) float g_z[N_PTS * EMB];
__device__ float g_sq[N_PTS];
__device__ float g_rowsum[N_PTS];

__device__ __forceinline__ float frcp(float x) {
    float r;
    asm("rcp.approx.ftz.f32 %0, %1;" : "=f"(r) : "f"(x));
    return r;
}
__device__ __forceinline__ void fma2(ull &d, ull a, ull b) {
    asm("fma.rn.f32x2 %0, %1, %2, %0;" : "+l"(d) : "l"(a), "l"(b));
}
__device__ __forceinline__ void unpack2(ull v, float &lo, float &hi) {
    asm("mov.b64 {%0, %1}, %2;" : "=f"(lo), "=f"(hi) : "l"(v));
}
__device__ __forceinline__ ull bcast2(float x) {
    ull v;
    asm("mov.b64 %0, {%1, %1};" : "=l"(v) : "f"(x));
    return v;
}

// 16B-chunk swizzle: logical row j -> physical ull slot (for j = 4tx+c mapping)
__device__ __forceinline__ int bswz(int j) {
    return 2 * ((j >> 2) + ((j >> 1) & 1) * 16) + (j & 1);
}

// triangular linear block id -> (row r, col c) with c >= r, 128x128 tile grid
__device__ __forceinline__ int tri_off128(int r) { return (r * (257 - r)) >> 1; }
__device__ __forceinline__ void tri_decode128(int b, int &r, int &c) {
    int rr = (int)((257.0f - sqrtf(66049.0f - 8.0f * (float)b)) * 0.5f);
    if (rr < 0) rr = 0;
    if (rr > 127) rr = 127;
    while (rr < 127 && tri_off128(rr + 1) <= b) rr++;
    while (rr > 0 && tri_off128(rr) > b) rr--;
    r = rr;
    c = rr + (b - tri_off128(rr));
}

// ===========================================================================
// Encoder: 256 blocks x 256 threads, 32 rows/block. (R5 version)
// ===========================================================================
#define OFF_W1   0            // float[128][64]   32768
#define OFF_X    32768        // float[32][132]   16896
#define OFF_W2   49664        // float[64][32]     8192
#define OFF_W3   57856        // float[32][16]     2048
#define OFF_W4   59904        // float[16][16]     1024
#define OFF_B1   60928        // 256
#define OFF_B2   61184        // 128
#define OFF_B3   61312        // 64
#define OFF_B4   61376        // 64
#define OFF_E1   61440        // float[32][68]     8704
#define OFF_E2   70144        // float[32][36]     4608
#define OFF_E3   74752        // float[32][20]     2560
#define ENC_SMEM 77312

__global__ __launch_bounds__(256) void encoder_kernel(
    const float* __restrict__ x,
    const float* __restrict__ W1, const float* __restrict__ b1,
    const float* __restrict__ W2, const float* __restrict__ b2,
    const float* __restrict__ W3, const float* __restrict__ b3,
    const float* __restrict__ W4, const float* __restrict__ b4)
{
    extern __shared__ char dyn[];
    float* sW1 = (float*)(dyn + OFF_W1);
    float* sx  = (float*)(dyn + OFF_X);
    float* sW2 = (float*)(dyn + OFF_W2);
    float* sW3 = (float*)(dyn + OFF_W3);
    float* sW4 = (float*)(dyn + OFF_W4);
    float* sb1 = (float*)(dyn + OFF_B1);
    float* sb2 = (float*)(dyn + OFF_B2);
    float* sb3 = (float*)(dyn + OFF_B3);
    float* sb4 = (float*)(dyn + OFF_B4);
    float* e1  = (float*)(dyn + OFF_E1);
    float* e2  = (float*)(dyn + OFF_E2);
    float* e3  = (float*)(dyn + OFF_E3);

    const int t  = threadIdx.x;
    const int i0 = blockIdx.x * 32;

    int gid = blockIdx.x * 256 + t;
    if (gid < N_PTS) g_rowsum[gid] = 0.0f;

    {
        const ulonglong2* s = (const ulonglong2*)W1;
        ulonglong2* d = (ulonglong2*)sW1;
        #pragma unroll
        for (int r = 0; r < 8; r++) d[t + r * 256] = s[t + r * 256];
    }
    {
        const float4* x4 = (const float4*)(x + (size_t)i0 * DIM);
        #pragma unroll
        for (int r = 0; r < 4; r++) {
            int idx = t + r * 256;
            int row = idx >> 5, c = idx & 31;
            *(float4*)&sx[row * 132 + c * 4] = x4[idx];
        }
    }
    {
        const float4* s = (const float4*)W2;
        float4* d = (float4*)sW2;
        d[t] = s[t]; d[t + 256] = s[t + 256];
    }
    if (t < 128) ((float4*)sW3)[t] = ((const float4*)W3)[t];
    if (t < 64)  ((float4*)sW4)[t] = ((const float4*)W4)[t];
    if (t < 64) sb1[t] = b1[t];
    if (t < 32) sb2[t] = b2[t];
    if (t < 16) { sb3[t] = b3[t]; sb4[t] = b4[t]; }
    __syncthreads();

    {
        const int og = t & 15, rg = t >> 4;
        const int r0 = rg * 2, r1 = r0 + 1;
        ull a00 = ((const ull*)sb1)[og * 2];
        ull a01 = ((const ull*)sb1)[og * 2 + 1];
        ull a10 = a00, a11 = a01;
        const ull* w1u = (const ull*)sW1;
        #pragma unroll 4
        for (int k4 = 0; k4 < 32; k4++) {
            float4 x0 = *(const float4*)&sx[r0 * 132 + k4 * 4];
            float4 x1 = *(const float4*)&sx[r1 * 132 + k4 * 4];
            float xs0[4] = {x0.x, x0.y, x0.z, x0.w};
            float xs1[4] = {x1.x, x1.y, x1.z, x1.w};
            #pragma unroll
            for (int c = 0; c < 4; c++) {
                ulonglong2 w = *(const ulonglong2*)&w1u[(k4 * 4 + c) * 32 + og * 2];
                ull v0 = bcast2(xs0[c]);
                ull v1 = bcast2(xs1[c]);
                fma2(a00, v0, w.x); fma2(a01, v0, w.y);
                fma2(a10, v1, w.x); fma2(a11, v1, w.y);
            }
        }
        float p, q, r, s;
        unpack2(a00, p, q); unpack2(a01, r, s);
        *(float4*)&e1[r0 * 68 + og * 4] =
            make_float4(fmaxf(p, 0.f), fmaxf(q, 0.f), fmaxf(r, 0.f), fmaxf(s, 0.f));
        unpack2(a10, p, q); unpack2(a11, r, s);
        *(float4*)&e1[r1 * 68 + og * 4] =
            make_float4(fmaxf(p, 0.f), fmaxf(q, 0.f), fmaxf(r, 0.f), fmaxf(s, 0.f));
    }
    __syncthreads();

    const int row = t >> 3;
    const int e   = t & 7;

    {
        ull c0 = ((const ull*)sb2)[e * 2];
        ull c1 = ((const ull*)sb2)[e * 2 + 1];
        const float* h1r = &e1[row * 68];
        const ull* w2u = (const ull*)sW2;
        #pragma unroll 4
        for (int k4 = 0; k4 < 16; k4++) {
            float4 h = *(const float4*)&h1r[k4 * 4];
            float hs[4] = {h.x, h.y, h.z, h.w};
            #pragma unroll
            for (int c = 0; c < 4; c++) {
                ulonglong2 w = *(const ulonglong2*)&w2u[(k4 * 4 + c) * 16 + e * 2];
                ull hb = bcast2(hs[c]);
                fma2(c0, hb, w.x); fma2(c1, hb, w.y);
            }
        }
        float p, q, r, s;
        unpack2(c0, p, q); unpack2(c1, r, s);
        *(float4*)&e2[row * 36 + e * 4] =
            make_float4(fmaxf(p, 0.f), fmaxf(q, 0.f), fmaxf(r, 0.f), fmaxf(s, 0.f));
    }
    __syncthreads();

    {
        ull d0 = ((const ull*)sb3)[e];
        const float* h2r = &e2[row * 36];
        const ull* w3u = (const ull*)sW3;
        #pragma unroll
        for (int k4 = 0; k4 < 8; k4++) {
            float4 h = *(const float4*)&h2r[k4 * 4];
            float hs[4] = {h.x, h.y, h.z, h.w};
            #pragma unroll
            for (int c = 0; c < 4; c++) {
                ull w = w3u[(k4 * 4 + c) * 8 + e];
                fma2(d0, bcast2(hs[c]), w);
            }
        }
        float p, q;
        unpack2(d0, p, q);
        *(float2*)&e3[row * 20 + e * 2] = make_float2(fmaxf(p, 0.f), fmaxf(q, 0.f));
    }
    __syncthreads();

    {
        ull f0 = ((const ull*)sb4)[e];
        const float* h3r = &e3[row * 20];
        const ull* w4u = (const ull*)sW4;
        #pragma unroll
        for (int k4 = 0; k4 < 4; k4++) {
            float4 h = *(const float4*)&h3r[k4 * 4];
            float hs[4] = {h.x, h.y, h.z, h.w};
            #pragma unroll
            for (int c = 0; c < 4; c++) {
                ull w = w4u[(k4 * 4 + c) * 8 + e];
                fma2(f0, bcast2(hs[c]), w);
            }
        }
        float z0, z1;
        unpack2(f0, z0, z1);
        *(float2*)&g_z[(size_t)(i0 + row) * EMB + e * 2] = make_float2(z0, z1);

        float ps = z0 * z0 + z1 * z1;
        ps += __shfl_xor_sync(0xffffffffu, ps, 1);
        ps += __shfl_xor_sync(0xffffffffu, ps, 2);
        ps += __shfl_xor_sync(0xffffffffu, ps, 4);
        if (e == 0) g_sq[i0 + row] = ps;
    }
}

// ===========================================================================
// Shared staging for 64-row tiles
// ===========================================================================
// plain layout (rowsum): slot = row
__device__ __forceinline__ void stage64(ull (*zsm)[66], int r0, int t) {
    const float4* gz4 = (const float4*)g_z;
    int row = t >> 2, q = t & 3;
    float4 f = gz4[(size_t)(r0 + row) * 4 + q];
    *(float2*)&zsm[2 * q][row]     = make_float2(f.x, f.y);
    *(float2*)&zsm[2 * q + 1][row] = make_float2(f.z, f.w);
}
// swizzled layout (writer b-tile): slot = bswz(row), consumed at 2tx / 32+2tx
__device__ __forceinline__ void stage64_swz(ull (*zsm)[66], int r0, int t) {
    const float4* gz4 = (const float4*)g_z;
    int row = t >> 2, q = t & 3;
    float4 f = gz4[(size_t)(r0 + row) * 4 + q];
    int p = bswz(row);
    *(float2*)&zsm[2 * q][p]     = make_float2(f.x, f.y);
    *(float2*)&zsm[2 * q + 1][p] = make_float2(f.z, f.w);
}

// rowsum inner 4i x 4j: j = tx + 16c (plain layout)
__device__ __forceinline__ void mma44(ull* acc, const ull (*zasm)[66],
                                      const ull (*zbsm)[66], int tx, int ty) {
    #pragma unroll
    for (int k2 = 0; k2 < 8; k2++) {
        ull b0 = zbsm[k2][tx];
        ull b1 = zbsm[k2][tx + 16];
        ull b2 = zbsm[k2][tx + 32];
        ull b3 = zbsm[k2][tx + 48];
        ulonglong2 a01 = *(const ulonglong2*)&zasm[k2][ty * 4];
        ulonglong2 a23 = *(const ulonglong2*)&zasm[k2][ty * 4 + 2];
        ull av[4] = {a01.x, a01.y, a23.x, a23.y};
        #pragma unroll
        for (int ii = 0; ii < 4; ii++) {
            fma2(acc[ii * 4 + 0], av[ii], b0);
            fma2(acc[ii * 4 + 1], av[ii], b1);
            fma2(acc[ii * 4 + 2], av[ii], b2);
            fma2(acc[ii * 4 + 3], av[ii], b3);
        }
    }
}

// writer inner 4i x 4j: j = 4tx + c (swizzled layout, LDS.128 pairs)
__device__ __forceinline__ void mma44_swz(ull* acc, const ull (*zasm)[66],
                                          const ull (*zbsm)[66], int tx, int ty) {
    #pragma unroll
    for (int k2 = 0; k2 < 8; k2++) {
        ulonglong2 b01 = *(const ulonglong2*)&zbsm[k2][2 * tx];       // j=4tx,4tx+1
        ulonglong2 b23 = *(const ulonglong2*)&zbsm[k2][32 + 2 * tx];  // j=4tx+2,4tx+3
        ulonglong2 a01 = *(const ulonglong2*)&zasm[k2][ty * 4];
        ulonglong2 a23 = *(const ulonglong2*)&zasm[k2][ty * 4 + 2];
        ull av[4] = {a01.x, a01.y, a23.x, a23.y};
        #pragma unroll
        for (int ii = 0; ii < 4; ii++) {
            fma2(acc[ii * 4 + 0], av[ii], b01.x);
            fma2(acc[ii * 4 + 1], av[ii], b01.y);
            fma2(acc[ii * 4 + 2], av[ii], b23.x);
            fma2(acc[ii * 4 + 3], av[ii], b23.y);
        }
    }
}

// ===========================================================================
// Kernel 2: symmetric row sums. triangular grid over 64x64 tiles (8256 blk).
// (exact R5 version)
// ===========================================================================
__global__ __launch_bounds__(256) void rowsum_kernel()
{
    int by, bx;
    tri_decode128(blockIdx.x, by, bx);

    __shared__ ull zasm[8][66];
    __shared__ ull zbsm[8][66];
    __shared__ float sqis[64];
    __shared__ float sqjs[64];
    __shared__ float rowacc[64];
    __shared__ float colacc[64];

    const int t = threadIdx.x, tx = t & 15, ty = t >> 4;
    const int i0 = by * 64, j0 = bx * 64;
    const bool diag = (bx == by);

    stage64(zasm, i0, t);
    stage64(zbsm, j0, t);
    if (t < 64) sqis[t] = g_sq[i0 + t];
    else if (t < 128) sqjs[t - 64] = g_sq[j0 + (t - 64)];
    else if (t < 192) colacc[t - 128] = 0.0f;
    __syncthreads();

    ull acc[16];
    #pragma unroll
    for (int m = 0; m < 16; m++) acc[m] = 0ull;
    mma44(acc, zasm, zbsm, tx, ty);

    const float sj0 = sqjs[tx];
    const float sj1 = sqjs[tx + 16];
    const float sj2 = sqjs[tx + 32];
    const float sj3 = sqjs[tx + 48];
    float colp0 = 0.f, colp1 = 0.f, colp2 = 0.f, colp3 = 0.f;

    #pragma unroll
    for (int ii = 0; ii < 4; ii++) {
        const float si = sqis[ty * 4 + ii];
        float lo, hi, dot, dist, n0, n1, n2, n3;
        unpack2(acc[ii * 4 + 0], lo, hi); dot = lo + hi;
        dist = fmaxf(fmaf(-2.0f, dot, si + sj0), 0.0f); n0 = frcp(1.0f + dist);
        unpack2(acc[ii * 4 + 1], lo, hi); dot = lo + hi;
        dist = fmaxf(fmaf(-2.0f, dot, si + sj1), 0.0f); n1 = frcp(1.0f + dist);
        unpack2(acc[ii * 4 + 2], lo, hi); dot = lo + hi;
        dist = fmaxf(fmaf(-2.0f, dot, si + sj2), 0.0f); n2 = frcp(1.0f + dist);
        unpack2(acc[ii * 4 + 3], lo, hi); dot = lo + hi;
        dist = fmaxf(fmaf(-2.0f, dot, si + sj3), 0.0f); n3 = frcp(1.0f + dist);

        float v = (n0 + n1) + (n2 + n3);
        v += __shfl_xor_sync(0xffffffffu, v, 1);
        v += __shfl_xor_sync(0xffffffffu, v, 2);
        v += __shfl_xor_sync(0xffffffffu, v, 4);
        v += __shfl_xor_sync(0xffffffffu, v, 8);
        if (tx == 0) rowacc[ty * 4 + ii] = v;

        colp0 += n0; colp1 += n1; colp2 += n2; colp3 += n3;
    }

    if (!diag) {
        colp0 += __shfl_xor_sync(0xffffffffu, colp0, 16);
        colp1 += __shfl_xor_sync(0xffffffffu, colp1, 16);
        colp2 += __shfl_xor_sync(0xffffffffu, colp2, 16);
        colp3 += __shfl_xor_sync(0xffffffffu, colp3, 16);
        if ((t & 16) == 0) {
            atomicAdd(&colacc[tx],      colp0);
            atomicAdd(&colacc[tx + 16], colp1);
            atomicAdd(&colacc[tx + 32], colp2);
            atomicAdd(&colacc[tx + 48], colp3);
        }
    }
    __syncthreads();

    if (t < 64) atomicAdd(&g_rowsum[i0 + t], rowacc[t]);
    if (!diag && t >= 64 && t < 128) atomicAdd(&g_rowsum[j0 + (t - 64)], colacc[t - 64]);
}

// ===========================================================================
// Kernel 3: symmetric writer. triangular grid (8256 blocks), 256 threads.
// j = 4tx+c mapping: epilogue does STS.128 (snum) + STG.128 (normal tile)
// directly from registers, overlapped with compute. Transposed phase = R5.
// ===========================================================================
__global__ __launch_bounds__(256) void writer_kernel(float* __restrict__ out)
{
    int by, bx;
    tri_decode128(blockIdx.x, by, bx);

    __shared__ ull zasm[8][66];
    __shared__ ull zbsm[8][66];
    __shared__ float snum[64 * 68];
    __shared__ float sqis[64];
    __shared__ float sqjs[64];
    __shared__ float rinvi[64];
    __shared__ float rinvj[64];

    const int t = threadIdx.x, tx = t & 15, ty = t >> 4;
    const int i0 = by * 64, j0 = bx * 64;
    const bool diag = (bx == by);

    stage64(zasm, i0, t);
    stage64_swz(zbsm, j0, t);
    if (t < 64) sqis[t] = g_sq[i0 + t];
    else if (t < 128) sqjs[t - 64] = g_sq[j0 + (t - 64)];
    else if (t < 192) rinvi[t - 128] = frcp(g_rowsum[i0 + (t - 128)]);
    else rinvj[t - 192] = frcp(g_rowsum[j0 + (t - 192)]);
    __syncthreads();

    ull acc[16];
    #pragma unroll
    for (int m = 0; m < 16; m++) acc[m] = 0ull;
    mma44_swz(acc, zasm, zbsm, tx, ty);

    const float4 sj4 = *(const float4*)&sqjs[4 * tx];

    #pragma unroll
    for (int ii = 0; ii < 4; ii++) {
        const int irow = ty * 4 + ii;
        const float si = sqis[irow];
        const float rvi = rinvi[irow];
        float lo, hi, dot, dist;
        float4 n;

        unpack2(acc[ii * 4 + 0], lo, hi); dot = lo + hi;
        dist = fmaxf(fmaf(-2.0f, dot, si + sj4.x), 0.0f); n.x = frcp(1.0f + dist);
        unpack2(acc[ii * 4 + 1], lo, hi); dot = lo + hi;
        dist = fmaxf(fmaf(-2.0f, dot, si + sj4.y), 0.0f); n.y = frcp(1.0f + dist);
        unpack2(acc[ii * 4 + 2], lo, hi); dot = lo + hi;
        dist = fmaxf(fmaf(-2.0f, dot, si + sj4.z), 0.0f); n.z = frcp(1.0f + dist);
        unpack2(acc[ii * 4 + 3], lo, hi); dot = lo + hi;
        dist = fmaxf(fmaf(-2.0f, dot, si + sj4.w), 0.0f); n.w = frcp(1.0f + dist);

        // stage numerators for transposed phase (STS.128, conflict-free per phase)
        *(float4*)&snum[irow * 68 + 4 * tx] = n;

        // normal tile store (STG.128, contiguous 16B/lane)
        float4 v = make_float4(n.x * rvi, n.y * rvi, n.z * rvi, n.w * rvi);
        *(float4*)&out[(size_t)(i0 + irow) * N_PTS + j0 + 4 * tx] = v;
    }

    if (!diag) {
        __syncthreads();
        #pragma unroll
        for (int ii = 0; ii < 4; ii++) {
            const int jrow = ty * 4 + ii;
            const float rvj = rinvj[jrow];
            float* orow = &out[(size_t)(j0 + jrow) * N_PTS + i0];
            orow[tx]      = snum[(tx)      * 68 + jrow] * rvj;
            orow[tx + 16] = snum[(tx + 16) * 68 + jrow] * rvj;
            orow[tx + 32] = snum[(tx + 32) * 68 + jrow] * rvj;
            orow[tx + 48] = snum[(tx + 48) * 68 + jrow] * rvj;
        }
    }
}

// ---------------------------------------------------------------------------
extern "C" void kernel_launch(void* const* d_in, const int* in_sizes, int n_in,
                              void* d_out, int out_size)
{
    const float* x  = (const float*)d_in[0];
    const float* W1 = (const float*)d_in[1];
    const float* b1 = (const float*)d_in[2];
    const float* W2 = (const float*)d_in[3];
    const float* b2 = (const float*)d_in[4];
    const float* W3 = (const float*)d_in[5];
    const float* b3 = (const float*)d_in[6];
    const float* W4 = (const float*)d_in[7];
    const float* b4 = (const float*)d_in[8];
    float* out = (float*)d_out;

    cudaFuncSetAttribute(encoder_kernel,
                         cudaFuncAttributeMaxDynamicSharedMemorySize, ENC_SMEM);

    const int n_tri = (128 * 129) / 2;  // 8256

    encoder_kernel<<<N_PTS / 32, 256, ENC_SMEM>>>(x, W1, b1, W2, b2, W3, b3, W4, b4);
    rowsum_kernel<<<n_tri, 256>>>();
    writer_kernel<<<n_tri, 256>>>(out);
}